// round 1
// baseline (speedup 1.0000x reference)
#include <cuda_runtime.h>

#define NN 100000
#define EE 1600000
#define C 64
#define HIDN 128
#define NEG 0.2f

#define MAX_L2  4096         // in-edges of target
#define MAX_S1  4100         // 1-hop set (srcs of target in-edges + target)
#define MAX_L1  262144       // in-edges of S1 nodes
#define MAX_DEG2 160         // layer-2 edges processed in tail block

// ---- scratch (device globals; zero-initialized at load; every launch restores
// ---- the zero state at the end of k_tail, so replays are deterministic) ----
__device__ int   g_slot[NN];                  // 0=unset, s+1 = slot s
__device__ int   g_l2e[MAX_L2];
__device__ int   g_l2cnt;
__device__ int   g_s1[MAX_S1];
__device__ int   g_s1cnt;
__device__ int   g_l1e[MAX_L1];
__device__ int   g_l1cnt;
__device__ float g_easum;
__device__ float g_escore[MAX_L1 + MAX_S1];   // layer-1 edge scores (+ self-loops)
__device__ int   g_nmax[MAX_S1];              // per-node max score (ordered-int key)
__device__ float g_ndenom[MAX_S1];
__device__ float g_nacc[MAX_S1 * C];
__device__ float g_h1[MAX_S1 * C];

__device__ __forceinline__ int fkey(float f) {
    int i = __float_as_int(f);
    return i < 0 ? (i ^ 0x7fffffff) : i;
}
__device__ __forceinline__ float finv(int k) {
    return __int_as_float(k < 0 ? (k ^ 0x7fffffff) : k);
}

// block-wide sum for blockDim==64, result broadcast to all threads
__device__ __forceinline__ float reduce64(float v, volatile float* sh) {
#pragma unroll
    for (int off = 16; off > 0; off >>= 1)
        v += __shfl_xor_sync(0xffffffffu, v, off);
    if ((threadIdx.x & 31) == 0) sh[threadIdx.x >> 5] = v;
    __syncthreads();
    float r = sh[0] + sh[1];
    __syncthreads();
    return r;
}

// ---- pass 1: sum(edge_attr); collect in-edges of target --------------------
__global__ void k_scan1(const int* __restrict__ ei, const float* __restrict__ ea,
                        const int* __restrict__ tgtp) {
    int i = blockIdx.x * blockDim.x + threadIdx.x;
    float v = 0.f;
    if (i < EE / 4) {
        const float4 a = reinterpret_cast<const float4*>(ea)[i];
        v = (a.x + a.y) + (a.z + a.w);
        const int4 d = reinterpret_cast<const int4*>(ei + EE)[i];
        int tgt = tgtp[0];
        int base = i * 4;
        if (d.x == tgt) { int p = atomicAdd(&g_l2cnt, 1); if (p < MAX_L2) g_l2e[p] = base; }
        if (d.y == tgt) { int p = atomicAdd(&g_l2cnt, 1); if (p < MAX_L2) g_l2e[p] = base + 1; }
        if (d.z == tgt) { int p = atomicAdd(&g_l2cnt, 1); if (p < MAX_L2) g_l2e[p] = base + 2; }
        if (d.w == tgt) { int p = atomicAdd(&g_l2cnt, 1); if (p < MAX_L2) g_l2e[p] = base + 3; }
    }
#pragma unroll
    for (int off = 16; off > 0; off >>= 1)
        v += __shfl_xor_sync(0xffffffffu, v, off);
    __shared__ float ws[8];
    if ((threadIdx.x & 31) == 0) ws[threadIdx.x >> 5] = v;
    __syncthreads();
    if (threadIdx.x == 0) {
        float s = 0.f;
#pragma unroll
        for (int w = 0; w < 8; w++) s += ws[w];
        atomicAdd(&g_easum, s);
    }
}

// ---- build S1 set, assign slots, init per-node accumulators ----------------
__global__ void k_mark(const int* __restrict__ ei, const int* __restrict__ tgtp) {
    int cnt = min(g_l2cnt, MAX_L2);
    for (int i = threadIdx.x; i < cnt; i += blockDim.x) {
        int j = ei[g_l2e[i]];                         // src of an in-edge of target
        if (atomicCAS(&g_slot[j], 0, -1) == 0) {
            int p = atomicAdd(&g_s1cnt, 1);
            g_s1[p] = j;
        }
    }
    if (threadIdx.x == 0) {
        int t = tgtp[0];
        if (atomicCAS(&g_slot[t], 0, -1) == 0) {
            int p = atomicAdd(&g_s1cnt, 1);
            g_s1[p] = t;
        }
    }
    __syncthreads();
    int sc = min(g_s1cnt, MAX_S1);
    for (int i = threadIdx.x; i < sc; i += blockDim.x) {
        g_slot[g_s1[i]] = i + 1;
        g_nmax[i] = (int)0x80000000;                  // INT_MIN = -inf key
        g_ndenom[i] = 0.f;
    }
    for (int i = threadIdx.x; i < sc * C; i += blockDim.x)
        g_nacc[i] = 0.f;
}

// ---- pass 2: collect all in-edges of S1 nodes ------------------------------
__global__ void k_scan2(const int* __restrict__ ei) {
    int i = blockIdx.x * blockDim.x + threadIdx.x;
    if (i < EE / 4) {
        const int4 d = reinterpret_cast<const int4*>(ei + EE)[i];
        int base = i * 4;
        if (g_slot[d.x] > 0) { int p = atomicAdd(&g_l1cnt, 1); if (p < MAX_L1) g_l1e[p] = base; }
        if (g_slot[d.y] > 0) { int p = atomicAdd(&g_l1cnt, 1); if (p < MAX_L1) g_l1e[p] = base + 1; }
        if (g_slot[d.z] > 0) { int p = atomicAdd(&g_l1cnt, 1); if (p < MAX_L1) g_l1e[p] = base + 2; }
        if (g_slot[d.w] > 0) { int p = atomicAdd(&g_l1cnt, 1); if (p < MAX_L1) g_l1e[p] = base + 3; }
    }
}

// ---- layer-1 pass A: per-edge scores + segment max -------------------------
__global__ void __launch_bounds__(64) k_e1a(
    const int* __restrict__ ei, const float* __restrict__ ea,
    const float* __restrict__ x,
    const float* __restrict__ Wl1, const float* __restrict__ bl1,
    const float* __restrict__ Wr1, const float* __restrict__ br1,
    const float* __restrict__ We1, const float* __restrict__ att1) {
    int c = threadIdx.x;
    __shared__ float s_red[2];
    int m = min(g_l1cnt, MAX_L1);
    int sc1 = min(g_s1cnt, MAX_S1);
    int total = m + sc1;                              // real edges + self-loops
    float ea_mean = g_easum * (1.f / (float)EE);
    float Wl0 = Wl1[c], Wl1c = Wl1[C + c], blc = bl1[c];
    float Wr0 = Wr1[c], Wr1c = Wr1[C + c], brc = br1[c];
    float Wec = We1[c], attc = att1[c];
    for (int idx = blockIdx.x; idx < total; idx += gridDim.x) {
        int j, dst; float eav;
        if (idx < m) {
            int e = g_l1e[idx];
            j = ei[e]; dst = ei[EE + e]; eav = ea[e];
        } else {
            int nd = g_s1[idx - m];
            j = nd; dst = nd; eav = ea_mean;
        }
        float xl = x[2 * j] * Wl0 + x[2 * j + 1] * Wl1c + blc;
        float xr = x[2 * dst] * Wr0 + x[2 * dst + 1] * Wr1c + brc;
        float t = xl + xr + eav * Wec;
        t = t >= 0.f ? t : NEG * t;
        float sc = reduce64(t * attc, s_red);
        if (c == 0) {
            g_escore[idx] = sc;
            atomicMax(&g_nmax[g_slot[dst] - 1], fkey(sc));
        }
    }
}

// ---- layer-1 pass B: softmax weights, segment sums -------------------------
__global__ void __launch_bounds__(64) k_e1b(
    const int* __restrict__ ei, const float* __restrict__ x,
    const float* __restrict__ Wl1, const float* __restrict__ bl1) {
    int c = threadIdx.x;
    int m = min(g_l1cnt, MAX_L1);
    int sc1 = min(g_s1cnt, MAX_S1);
    int total = m + sc1;
    float Wl0 = Wl1[c], Wl1c = Wl1[C + c], blc = bl1[c];
    for (int idx = blockIdx.x; idx < total; idx += gridDim.x) {
        int j, dst;
        if (idx < m) {
            int e = g_l1e[idx];
            j = ei[e]; dst = ei[EE + e];
        } else {
            int nd = g_s1[idx - m];
            j = nd; dst = nd;
        }
        int slot = g_slot[dst] - 1;
        float w = expf(g_escore[idx] - finv(g_nmax[slot]));
        float xl = x[2 * j] * Wl0 + x[2 * j + 1] * Wl1c + blc;
        atomicAdd(&g_nacc[slot * C + c], w * xl);
        if (c == 0) atomicAdd(&g_ndenom[slot], w);
    }
}

// ---- tail: finalize h1, layer 2 on target, final head, scratch cleanup -----
__global__ void __launch_bounds__(64) k_tail(
    const int* __restrict__ ei, const float* __restrict__ ea,
    const int* __restrict__ tgtp, const float* __restrict__ b1,
    const float* __restrict__ Wl2, const float* __restrict__ bl2,
    const float* __restrict__ Wr2, const float* __restrict__ br2,
    const float* __restrict__ We2, const float* __restrict__ att2,
    const float* __restrict__ b2,
    const float* __restrict__ Wf, const float* __restrict__ bf,
    float* __restrict__ out) {
    int c = threadIdx.x;
    int sc1 = min(g_s1cnt, MAX_S1);

    // finalize layer-1: h1 = relu(acc/denom + b1)
    float b1c = b1[c];
    for (int s = 0; s < sc1; s++) {
        float v = g_nacc[s * C + c] / g_ndenom[s] + b1c;
        g_h1[s * C + c] = fmaxf(v, 0.f);
    }
    __syncthreads();

    int tgt = tgtp[0];
    int ts = g_slot[tgt] - 1;
    float ea_mean = g_easum * (1.f / (float)EE);

    __shared__ float s_h1t[C];
    __shared__ float s_xl[MAX_DEG2 * C];
    __shared__ float s_sc[MAX_DEG2];
    __shared__ float s_red[2];
    __shared__ float s_h2[C];

    s_h1t[c] = g_h1[ts * C + c];
    __syncthreads();

    // xr for target (4 accumulators to break the FMA chain)
    float xr;
    {
        float a0 = 0.f, a1 = 0.f, a2 = 0.f, a3 = 0.f;
#pragma unroll
        for (int k = 0; k < C; k += 4) {
            a0 += s_h1t[k]     * Wr2[(k)     * C + c];
            a1 += s_h1t[k + 1] * Wr2[(k + 1) * C + c];
            a2 += s_h1t[k + 2] * Wr2[(k + 2) * C + c];
            a3 += s_h1t[k + 3] * Wr2[(k + 3) * C + c];
        }
        xr = br2[c] + ((a0 + a1) + (a2 + a3));
    }

    float attc = att2[c], Wec = We2[c], blc = bl2[c];
    int m2 = min(g_l2cnt, MAX_L2);
    int deg = 0;
    float smax = -3.4e38f;
    for (int it = -1; it < m2 && deg < MAX_DEG2; it++) {
        int j; float eav;
        if (it < 0) { j = tgt; eav = ea_mean; }                 // self-loop
        else { int e = g_l2e[it]; j = ei[e]; eav = ea[e]; }
        const float* hrow = &g_h1[(g_slot[j] - 1) * C];
        float a0 = 0.f, a1 = 0.f, a2 = 0.f, a3 = 0.f;
#pragma unroll
        for (int k = 0; k < C; k += 4) {
            a0 += hrow[k]     * Wl2[(k)     * C + c];
            a1 += hrow[k + 1] * Wl2[(k + 1) * C + c];
            a2 += hrow[k + 2] * Wl2[(k + 2) * C + c];
            a3 += hrow[k + 3] * Wl2[(k + 3) * C + c];
        }
        float xl = blc + ((a0 + a1) + (a2 + a3));
        float t = xl + xr + eav * Wec;
        t = t >= 0.f ? t : NEG * t;
        float sc = reduce64(t * attc, s_red);
        s_xl[deg * C + c] = xl;
        if (c == 0) s_sc[deg] = sc;
        smax = fmaxf(smax, sc);
        deg++;
    }
    __syncthreads();

    float denom = 0.f, acc = 0.f;
    for (int k = 0; k < deg; k++) {
        float w = expf(s_sc[k] - smax);
        denom += w;
        acc += w * s_xl[k * C + c];
    }
    s_h2[c] = fmaxf(acc / denom + b2[c], 0.f);
    __syncthreads();

    // final head: each thread produces outputs c and c+64
    float o0 = bf[c], o1 = bf[c + 64];
#pragma unroll
    for (int k = 0; k < C; k++) {
        float h = s_h2[k];
        o0 += h * Wf[k * HIDN + c];
        o1 += h * Wf[k * HIDN + c + 64];
    }
    out[c] = o0;
    out[c + 64] = o1;

    // restore zero-state invariant for next (graph-replay) call
    __syncthreads();
    for (int i = c; i < sc1; i += C) g_slot[g_s1[i]] = 0;
    if (c == 0) { g_l2cnt = 0; g_s1cnt = 0; g_l1cnt = 0; g_easum = 0.f; }
}

extern "C" void kernel_launch(void* const* d_in, const int* in_sizes, int n_in,
                              void* d_out, int out_size) {
    const float* x    = (const float*)d_in[0];
    const int*   ei   = (const int*)d_in[1];
    const float* ea   = (const float*)d_in[2];
    const int*   tgt  = (const int*)d_in[3];   // low 32 bits correct for i32/i64
    const float* Wl1  = (const float*)d_in[4];
    const float* bl1  = (const float*)d_in[5];
    const float* Wr1  = (const float*)d_in[6];
    const float* br1  = (const float*)d_in[7];
    const float* We1  = (const float*)d_in[8];
    const float* att1 = (const float*)d_in[9];
    const float* b1   = (const float*)d_in[10];
    const float* Wl2  = (const float*)d_in[11];
    const float* bl2  = (const float*)d_in[12];
    const float* Wr2  = (const float*)d_in[13];
    const float* br2  = (const float*)d_in[14];
    const float* We2  = (const float*)d_in[15];
    const float* att2 = (const float*)d_in[16];
    const float* b2   = (const float*)d_in[17];
    const float* Wf   = (const float*)d_in[18];
    const float* bf   = (const float*)d_in[19];
    float* out = (float*)d_out;

    const int scan_blocks = (EE / 4 + 255) / 256;
    k_scan1<<<scan_blocks, 256>>>(ei, ea, tgt);
    k_mark<<<1, 256>>>(ei, tgt);
    k_scan2<<<scan_blocks, 256>>>(ei);
    k_e1a<<<512, 64>>>(ei, ea, x, Wl1, bl1, Wr1, br1, We1, att1);
    k_e1b<<<512, 64>>>(ei, x, Wl1, bl1);
    k_tail<<<1, 64>>>(ei, ea, tgt, b1, Wl2, bl2, Wr2, br2, We2, att2, b2, Wf, bf, out);
}

// round 2
// speedup vs baseline: 1.1017x; 1.1017x over previous
#include <cuda_runtime.h>

#define NN 100000
#define EE 1600000
#define EV (EE / 4)
#define C 64
#define HIDN 128
#define NEG 0.2f

#define NB 148            // persistent blocks (<= SM count -> co-resident)
#define NT 256
#define NGW (NB * 8)      // global warp count

#define MAX_L2   4096     // in-edges of target
#define MAX_S1   4100     // 1-hop source set + target
#define MAX_L1   262144   // in-edges of S1 nodes
#define MAX_DEG2 144      // layer-2 edges handled in tail
#define SH_S1    1024     // S1 entries cached in smem for the scan

// ---- scratch (device globals, zero at load; block 0 restores zero-state) ---
__device__ int      g_slot[NN];
__device__ int      g_l2e[MAX_L2];
__device__ int      g_l2cnt;
__device__ int      g_s1[MAX_S1];
__device__ int      g_s1cnt;
__device__ int      g_l1e[MAX_L1];
__device__ int      g_l1cnt;
__device__ float    g_eapart[NB];
__device__ float    g_easum;
__device__ float    g_escore[MAX_L1 + MAX_S1];
__device__ int      g_nmax[MAX_S1];
__device__ float    g_ndenom[MAX_S1];
__device__ float    g_nacc[MAX_S1 * C];
__device__ float    g_h1[MAX_S1 * C];
__device__ unsigned g_barc[8];
__device__ unsigned g_exit;

__device__ __forceinline__ int fkey(float f) {
    int i = __float_as_int(f);
    return i < 0 ? (i ^ 0x7fffffff) : i;
}
__device__ __forceinline__ float finv(int k) {
    return __int_as_float(k < 0 ? (k ^ 0x7fffffff) : k);
}
__device__ __forceinline__ float wred(float v) {
#pragma unroll
    for (int off = 16; off > 0; off >>= 1)
        v += __shfl_xor_sync(0xffffffffu, v, off);
    return v;
}
// grid barrier: counter k reset only after the g_exit handshake at the end
__device__ __forceinline__ void gbar(int k) {
    __syncthreads();
    if (threadIdx.x == 0) {
        __threadfence();
        atomicAdd(&g_barc[k], 1u);
        while (*((volatile unsigned*)&g_barc[k]) < NB) { }
        __threadfence();
    }
    __syncthreads();
}

__global__ void __launch_bounds__(NT, 1) k_fused(
    const float* __restrict__ x,   const int* __restrict__ ei,
    const float* __restrict__ ea,  const int* __restrict__ tgtp,
    const float* __restrict__ Wl1, const float* __restrict__ bl1,
    const float* __restrict__ Wr1, const float* __restrict__ br1,
    const float* __restrict__ We1, const float* __restrict__ att1,
    const float* __restrict__ b1,
    const float* __restrict__ Wl2, const float* __restrict__ bl2,
    const float* __restrict__ Wr2, const float* __restrict__ br2,
    const float* __restrict__ We2, const float* __restrict__ att2,
    const float* __restrict__ b2,
    const float* __restrict__ Wf,  const float* __restrict__ bf,
    float* __restrict__ out)
{
    const int tid  = threadIdx.x;
    const int bid  = blockIdx.x;
    const int lane = tid & 31;
    const int wid  = tid >> 5;
    const int gw   = bid * 8 + wid;
    const int gid  = bid * NT + tid;

    __shared__ float s_w[8];
    __shared__ int   s_s1[SH_S1];
    __shared__ float s_xr[C];
    __shared__ float s_h2[C];
    __shared__ float s_sc[MAX_DEG2];
    __shared__ float s_xl[MAX_DEG2 * C];

    const int tgt = tgtp[0];
    const int4*   dst4 = reinterpret_cast<const int4*>(ei + EE);
    const float4* ea4  = reinterpret_cast<const float4*>(ea);

    // ---- phase A: sum(edge_attr) partials + collect in-edges of target ----
    {
        float v = 0.f;
        for (int i = gid; i < EV; i += NB * NT) {
            const float4 a = ea4[i];
            v += (a.x + a.y) + (a.z + a.w);
            const int4 d = dst4[i];
            int base = i * 4;
            if (d.x == tgt) { int p = atomicAdd(&g_l2cnt, 1); if (p < MAX_L2) g_l2e[p] = base; }
            if (d.y == tgt) { int p = atomicAdd(&g_l2cnt, 1); if (p < MAX_L2) g_l2e[p] = base + 1; }
            if (d.z == tgt) { int p = atomicAdd(&g_l2cnt, 1); if (p < MAX_L2) g_l2e[p] = base + 2; }
            if (d.w == tgt) { int p = atomicAdd(&g_l2cnt, 1); if (p < MAX_L2) g_l2e[p] = base + 3; }
        }
        v = wred(v);
        if (lane == 0) s_w[wid] = v;
        __syncthreads();
        if (tid == 0) {
            float s = 0.f;
#pragma unroll
            for (int w = 0; w < 8; w++) s += s_w[w];
            g_eapart[bid] = s;
        }
    }
    gbar(0);

    // ---- phase B (block 0): easum, build S1 set, slots, init accumulators --
    if (bid == 0) {
        if (tid == 0) {
            float s = 0.f;
            for (int i = 0; i < NB; i++) s += g_eapart[i];
            g_easum = s;
        }
        int cnt = min(g_l2cnt, MAX_L2);
        for (int i = tid; i < cnt; i += NT) {
            int j = ei[g_l2e[i]];
            if (atomicCAS(&g_slot[j], 0, -1) == 0) {
                int p = atomicAdd(&g_s1cnt, 1);
                if (p < MAX_S1) g_s1[p] = j;
            }
        }
        if (tid == 0) {
            if (atomicCAS(&g_slot[tgt], 0, -1) == 0) {
                int p = atomicAdd(&g_s1cnt, 1);
                if (p < MAX_S1) g_s1[p] = tgt;
            }
        }
        __syncthreads();
        int sc = min(g_s1cnt, MAX_S1);
        for (int i = tid; i < sc; i += NT) {
            g_slot[g_s1[i]] = i + 1;
            g_nmax[i] = (int)0x80000000;
            g_ndenom[i] = 0.f;
        }
        for (int i = tid; i < sc * C; i += NT) g_nacc[i] = 0.f;
    }
    gbar(1);

    const int   sc1     = min(g_s1cnt, MAX_S1);
    const float ea_mean = g_easum * (1.f / (float)EE);

    // ---- phase C: collect in-edges of S1 (smem compare vs tiny list) ------
    {
        const bool use_sh = (sc1 <= SH_S1);
        if (use_sh) for (int i = tid; i < sc1; i += NT) s_s1[i] = g_s1[i];
        __syncthreads();
        for (int i = gid; i < EV; i += NB * NT) {
            const int4 d = dst4[i];
            bool h0 = false, h1 = false, h2 = false, h3 = false;
            if (use_sh) {
#pragma unroll 1
                for (int j = 0; j < sc1; j++) {
                    int s = s_s1[j];
                    h0 |= (d.x == s); h1 |= (d.y == s);
                    h2 |= (d.z == s); h3 |= (d.w == s);
                }
            } else {
                h0 = g_slot[d.x] > 0; h1 = g_slot[d.y] > 0;
                h2 = g_slot[d.z] > 0; h3 = g_slot[d.w] > 0;
            }
            int base = i * 4;
            if (h0) { int p = atomicAdd(&g_l1cnt, 1); if (p < MAX_L1) g_l1e[p] = base; }
            if (h1) { int p = atomicAdd(&g_l1cnt, 1); if (p < MAX_L1) g_l1e[p] = base + 1; }
            if (h2) { int p = atomicAdd(&g_l1cnt, 1); if (p < MAX_L1) g_l1e[p] = base + 2; }
            if (h3) { int p = atomicAdd(&g_l1cnt, 1); if (p < MAX_L1) g_l1e[p] = base + 3; }
        }
    }
    gbar(2);

    const int m1    = min(g_l1cnt, MAX_L1);
    const int total = m1 + sc1;                        // + self-loops
    const int c0 = lane, c1 = lane + 32;

    // ---- phase D: layer-1 scores + segment max (warp per edge) ------------
    {
        const float Wla0 = Wl1[c0], Wla1 = Wl1[C + c0], bla = bl1[c0];
        const float Wra0 = Wr1[c0], Wra1 = Wr1[C + c0], bra = br1[c0];
        const float Wea  = We1[c0], atta = att1[c0];
        const float Wlb0 = Wl1[c1], Wlb1 = Wl1[C + c1], blb = bl1[c1];
        const float Wrb0 = Wr1[c1], Wrb1 = Wr1[C + c1], brb = br1[c1];
        const float Web  = We1[c1], attb = att1[c1];
        for (int idx = gw; idx < total; idx += NGW) {
            int j, dst; float eav;
            if (idx < m1) { int e = g_l1e[idx]; j = ei[e]; dst = ei[EE + e]; eav = ea[e]; }
            else          { int nd = g_s1[idx - m1]; j = nd; dst = nd; eav = ea_mean; }
            float xj0 = x[2 * j], xj1 = x[2 * j + 1];
            float xd0 = x[2 * dst], xd1 = x[2 * dst + 1];
            float ta = (xj0 * Wla0 + xj1 * Wla1 + bla) + (xd0 * Wra0 + xd1 * Wra1 + bra) + eav * Wea;
            float tb = (xj0 * Wlb0 + xj1 * Wlb1 + blb) + (xd0 * Wrb0 + xd1 * Wrb1 + brb) + eav * Web;
            ta = ta >= 0.f ? ta : NEG * ta;
            tb = tb >= 0.f ? tb : NEG * tb;
            float s = wred(ta * atta + tb * attb);
            if (lane == 0) {
                g_escore[idx] = s;
                atomicMax(&g_nmax[g_slot[dst] - 1], fkey(s));
            }
        }
    }
    gbar(3);

    // ---- phase E: layer-1 softmax weights + segment sums ------------------
    {
        const float Wla0 = Wl1[c0], Wla1 = Wl1[C + c0], bla = bl1[c0];
        const float Wlb0 = Wl1[c1], Wlb1 = Wl1[C + c1], blb = bl1[c1];
        for (int idx = gw; idx < total; idx += NGW) {
            int j, dst;
            if (idx < m1) { int e = g_l1e[idx]; j = ei[e]; dst = ei[EE + e]; }
            else          { int nd = g_s1[idx - m1]; j = nd; dst = nd; }
            int slot = g_slot[dst] - 1;
            float w = expf(g_escore[idx] - finv(g_nmax[slot]));
            float xj0 = x[2 * j], xj1 = x[2 * j + 1];
            float xla = xj0 * Wla0 + xj1 * Wla1 + bla;
            float xlb = xj0 * Wlb0 + xj1 * Wlb1 + blb;
            atomicAdd(&g_nacc[slot * C + c0], w * xla);
            atomicAdd(&g_nacc[slot * C + c1], w * xlb);
            if (lane == 0) atomicAdd(&g_ndenom[slot], w);
        }
    }
    gbar(4);

    // ---- phase F (block 0): finalize h1, layer 2, head, cleanup -----------
    if (bid != 0) {
        __syncthreads();
        if (tid == 0) { __threadfence(); atomicAdd(&g_exit, 1u); }
        return;
    }

    // finalize h1 = relu(acc/denom + b1)
    for (int i = tid; i < sc1 * C; i += NT) {
        float v = g_nacc[i] / g_ndenom[i >> 6] + b1[i & 63];
        g_h1[i] = fmaxf(v, 0.f);
    }
    __syncthreads();

    const int ts = g_slot[tgt] - 1;

    // xr for target
    if (tid < C) {
        const float* h1t = &g_h1[ts * C];
        float a0 = 0.f, a1 = 0.f, a2 = 0.f, a3 = 0.f;
#pragma unroll
        for (int k = 0; k < C; k += 4) {
            a0 += h1t[k]     * Wr2[(k)     * C + tid];
            a1 += h1t[k + 1] * Wr2[(k + 1) * C + tid];
            a2 += h1t[k + 2] * Wr2[(k + 2) * C + tid];
            a3 += h1t[k + 3] * Wr2[(k + 3) * C + tid];
        }
        s_xr[tid] = br2[tid] + ((a0 + a1) + (a2 + a3));
    }
    __syncthreads();

    // layer-2 edges: warp per edge (idx 0 = self-loop)
    const int m2  = min(g_l2cnt, MAX_L2);
    const int deg = min(m2 + 1, MAX_DEG2);
    for (int idx = wid; idx < deg; idx += 8) {
        int j; float eav;
        if (idx == 0) { j = tgt; eav = ea_mean; }
        else          { int e = g_l2e[idx - 1]; j = ei[e]; eav = ea[e]; }
        const float* hrow = &g_h1[(g_slot[j] - 1) * C];
        float xla = bl2[c0], xlb = bl2[c1];
#pragma unroll 8
        for (int k = 0; k < C; k++) {
            float h = hrow[k];
            xla += h * Wl2[k * C + c0];
            xlb += h * Wl2[k * C + c1];
        }
        float ta = xla + s_xr[c0] + eav * We2[c0];
        float tb = xlb + s_xr[c1] + eav * We2[c1];
        ta = ta >= 0.f ? ta : NEG * ta;
        tb = tb >= 0.f ? tb : NEG * tb;
        float s = wred(ta * att2[c0] + tb * att2[c1]);
        s_xl[idx * C + c0] = xla;
        s_xl[idx * C + c1] = xlb;
        if (lane == 0) s_sc[idx] = s;
    }
    __syncthreads();

    if (tid < C) {
        float smax = -3.4e38f;
        for (int k = 0; k < deg; k++) smax = fmaxf(smax, s_sc[k]);
        float denom = 0.f, acc = 0.f;
        for (int k = 0; k < deg; k++) {
            float w = expf(s_sc[k] - smax);
            denom += w;
            acc   += w * s_xl[k * C + tid];
        }
        s_h2[tid] = fmaxf(acc / denom + b2[tid], 0.f);
    }
    __syncthreads();

    if (tid < HIDN) {
        float o = bf[tid];
#pragma unroll
        for (int k = 0; k < C; k++) o += s_h2[k] * Wf[k * HIDN + tid];
        out[tid] = o;
    }

    // ---- cleanup: restore zero-state for graph replay ---------------------
    __syncthreads();
    for (int i = tid; i < sc1; i += NT) g_slot[g_s1[i]] = 0;
    if (tid == 0) {
        g_l2cnt = 0; g_s1cnt = 0; g_l1cnt = 0; g_easum = 0.f;
        // wait until every other block has arrived past the last barrier
        while (*((volatile unsigned*)&g_exit) < NB - 1) { }
        __threadfence();
#pragma unroll
        for (int k = 0; k < 8; k++) g_barc[k] = 0;
        g_exit = 0;
        __threadfence();
    }
}

extern "C" void kernel_launch(void* const* d_in, const int* in_sizes, int n_in,
                              void* d_out, int out_size) {
    const float* x    = (const float*)d_in[0];
    const int*   ei   = (const int*)d_in[1];
    const float* ea   = (const float*)d_in[2];
    const int*   tgt  = (const int*)d_in[3];
    const float* Wl1  = (const float*)d_in[4];
    const float* bl1  = (const float*)d_in[5];
    const float* Wr1  = (const float*)d_in[6];
    const float* br1  = (const float*)d_in[7];
    const float* We1  = (const float*)d_in[8];
    const float* att1 = (const float*)d_in[9];
    const float* b1   = (const float*)d_in[10];
    const float* Wl2  = (const float*)d_in[11];
    const float* bl2  = (const float*)d_in[12];
    const float* Wr2  = (const float*)d_in[13];
    const float* br2  = (const float*)d_in[14];
    const float* We2  = (const float*)d_in[15];
    const float* att2 = (const float*)d_in[16];
    const float* b2   = (const float*)d_in[17];
    const float* Wf   = (const float*)d_in[18];
    const float* bf   = (const float*)d_in[19];
    float* out = (float*)d_out;

    k_fused<<<NB, NT>>>(x, ei, ea, tgt,
                        Wl1, bl1, Wr1, br1, We1, att1, b1,
                        Wl2, bl2, Wr2, br2, We2, att2, b2,
                        Wf, bf, out);
}

// round 3
// speedup vs baseline: 1.5333x; 1.3918x over previous
#include <cuda_runtime.h>

#define NN 100000
#define EE 1600000
#define EV (EE / 4)
#define C 64
#define HIDN 128
#define NEG 0.2f

#define NB 148            // persistent blocks (<= SM count -> co-resident)
#define NT 512
#define NWB 16            // warps per block
#define NGW (NB * NWB)

#define MAX_L2   4096     // in-edges of target
#define MAX_S1   4100     // 1-hop source set + target
#define MAX_L1   262144   // in-edges of S1 nodes
#define MAX_DEG2 144      // layer-2 edges handled in tail
#define HBITS    12
#define HSIZE    (1 << HBITS)      // smem hash slots
#define HMASK    (HSIZE - 1)
#define HASH_CAP 2048              // max S1 size served by the hash

// ---- scratch (device globals, zero at load; block 0 restores zero-state) ---
__device__ int      g_slot[NN];
__device__ int      g_l2e[MAX_L2];
__device__ int      g_l2cnt;
__device__ int      g_s1[MAX_S1];
__device__ int      g_s1cnt;
__device__ int      g_l1e[MAX_L1];
__device__ int      g_l1cnt;
__device__ float    g_eapart[NB];
__device__ float    g_easum;
__device__ float    g_escore[MAX_L1 + MAX_S1];
__device__ int      g_nmax[MAX_S1];
__device__ float    g_ndenom[MAX_S1];
__device__ float    g_nacc[MAX_S1 * C];
__device__ float    g_h1[MAX_S1 * C];
__device__ unsigned g_barc[8];
__device__ unsigned g_exit;

__device__ __forceinline__ int fkey(float f) {
    int i = __float_as_int(f);
    return i < 0 ? (i ^ 0x7fffffff) : i;
}
__device__ __forceinline__ float finv(int k) {
    return __int_as_float(k < 0 ? (k ^ 0x7fffffff) : k);
}
__device__ __forceinline__ float wred(float v) {
#pragma unroll
    for (int off = 16; off > 0; off >>= 1)
        v += __shfl_xor_sync(0xffffffffu, v, off);
    return v;
}
__device__ __forceinline__ unsigned hh(int v) {
    return ((unsigned)v * 2654435761u) >> (32 - HBITS);
}
// grid barrier: counter k reset only after the g_exit handshake at the end
__device__ __forceinline__ void gbar(int k) {
    __syncthreads();
    if (threadIdx.x == 0) {
        __threadfence();
        atomicAdd(&g_barc[k], 1u);
        while (*((volatile unsigned*)&g_barc[k]) < NB) { }
        __threadfence();
    }
    __syncthreads();
}

__global__ void __launch_bounds__(NT, 1) k_fused(
    const float* __restrict__ x,   const int* __restrict__ ei,
    const float* __restrict__ ea,  const int* __restrict__ tgtp,
    const float* __restrict__ Wl1, const float* __restrict__ bl1,
    const float* __restrict__ Wr1, const float* __restrict__ br1,
    const float* __restrict__ We1, const float* __restrict__ att1,
    const float* __restrict__ b1,
    const float* __restrict__ Wl2, const float* __restrict__ bl2,
    const float* __restrict__ Wr2, const float* __restrict__ br2,
    const float* __restrict__ We2, const float* __restrict__ att2,
    const float* __restrict__ b2,
    const float* __restrict__ Wf,  const float* __restrict__ bf,
    float* __restrict__ out)
{
    const int tid  = threadIdx.x;
    const int bid  = blockIdx.x;
    const int lane = tid & 31;
    const int wid  = tid >> 5;
    const int gw   = bid * NWB + wid;
    const int gid  = bid * NT + tid;

    // big buffer: phase C hash table (16KB) / phase F s_xl (36KB)
    __shared__ __align__(16) char s_big[MAX_DEG2 * C * 4];
    int*   s_hash = (int*)s_big;
    float* s_xl   = (float*)s_big;

    __shared__ float s_w[NWB];
    __shared__ float s_xr[C];
    __shared__ float s_h2[C];
    __shared__ float s_sc[MAX_DEG2];

    const int tgt = tgtp[0];
    const int4*   dst4 = reinterpret_cast<const int4*>(ei + EE);
    const float4* ea4  = reinterpret_cast<const float4*>(ea);
    const int stride = NB * NT;

    // ---- phase A: sum(edge_attr) partials + collect in-edges of target ----
    {
        float v = 0.f;
        for (int base = gid; base < EV; base += stride * 6) {
            int ii[6]; float4 a[6]; int4 d[6];
#pragma unroll
            for (int u = 0; u < 6; u++) ii[u] = base + u * stride;
#pragma unroll
            for (int u = 0; u < 6; u++) if (ii[u] < EV) a[u] = ea4[ii[u]];
#pragma unroll
            for (int u = 0; u < 6; u++) if (ii[u] < EV) d[u] = dst4[ii[u]];
#pragma unroll
            for (int u = 0; u < 6; u++) {
                if (ii[u] < EV) {
                    v += (a[u].x + a[u].y) + (a[u].z + a[u].w);
                    int b4 = ii[u] * 4;
                    if (d[u].x == tgt) { int p = atomicAdd(&g_l2cnt, 1); if (p < MAX_L2) g_l2e[p] = b4; }
                    if (d[u].y == tgt) { int p = atomicAdd(&g_l2cnt, 1); if (p < MAX_L2) g_l2e[p] = b4 + 1; }
                    if (d[u].z == tgt) { int p = atomicAdd(&g_l2cnt, 1); if (p < MAX_L2) g_l2e[p] = b4 + 2; }
                    if (d[u].w == tgt) { int p = atomicAdd(&g_l2cnt, 1); if (p < MAX_L2) g_l2e[p] = b4 + 3; }
                }
            }
        }
        v = wred(v);
        if (lane == 0) s_w[wid] = v;
        __syncthreads();
        if (tid == 0) {
            float s = 0.f;
#pragma unroll
            for (int w = 0; w < NWB; w++) s += s_w[w];
            g_eapart[bid] = s;
        }
    }
    gbar(0);

    // ---- phase B (block 0): easum, build S1 set, slots, init accumulators --
    if (bid == 0) {
        if (tid == 0) {
            float s = 0.f;
            for (int i = 0; i < NB; i++) s += g_eapart[i];
            g_easum = s;
        }
        int cnt = min(g_l2cnt, MAX_L2);
        for (int i = tid; i < cnt; i += NT) {
            int j = ei[g_l2e[i]];
            if (atomicCAS(&g_slot[j], 0, -1) == 0) {
                int p = atomicAdd(&g_s1cnt, 1);
                if (p < MAX_S1) g_s1[p] = j;
            }
        }
        if (tid == 0) {
            if (atomicCAS(&g_slot[tgt], 0, -1) == 0) {
                int p = atomicAdd(&g_s1cnt, 1);
                if (p < MAX_S1) g_s1[p] = tgt;
            }
        }
        __syncthreads();
        int sc = min(g_s1cnt, MAX_S1);
        for (int i = tid; i < sc; i += NT) {
            g_slot[g_s1[i]] = i + 1;
            g_nmax[i] = (int)0x80000000;
            g_ndenom[i] = 0.f;
        }
        for (int i = tid; i < sc * C; i += NT) g_nacc[i] = 0.f;
    }
    gbar(1);

    const int   sc1     = min(g_s1cnt, MAX_S1);
    const float ea_mean = g_easum * (1.f / (float)EE);
    const bool  use_hash = (sc1 <= HASH_CAP);

    // ---- phase C: collect in-edges of S1 via smem hash ---------------------
    {
        if (use_hash) {
            for (int i = tid; i < HSIZE; i += NT) s_hash[i] = -1;
            __syncthreads();
            for (int i = tid; i < sc1; i += NT) {
                int v = g_s1[i];
                unsigned h = hh(v);
                while (atomicCAS(&s_hash[h], -1, v) != -1) h = (h + 1) & HMASK;
            }
        }
        __syncthreads();
        for (int base = gid; base < EV; base += stride * 6) {
            int ii[6]; int4 d[6];
#pragma unroll
            for (int u = 0; u < 6; u++) ii[u] = base + u * stride;
#pragma unroll
            for (int u = 0; u < 6; u++) if (ii[u] < EV) d[u] = dst4[ii[u]];
#pragma unroll
            for (int u = 0; u < 6; u++) {
                if (ii[u] < EV) {
                    bool h0, h1, h2, h3;
                    if (use_hash) {
                        int vv[4] = {d[u].x, d[u].y, d[u].z, d[u].w};
                        bool hit[4];
#pragma unroll
                        for (int q = 0; q < 4; q++) {
                            unsigned h = hh(vv[q]);
                            bool f = false;
                            while (true) {
                                int e = s_hash[h];
                                if (e == vv[q]) { f = true; break; }
                                if (e == -1) break;
                                h = (h + 1) & HMASK;
                            }
                            hit[q] = f;
                        }
                        h0 = hit[0]; h1 = hit[1]; h2 = hit[2]; h3 = hit[3];
                    } else {
                        h0 = g_slot[d[u].x] > 0; h1 = g_slot[d[u].y] > 0;
                        h2 = g_slot[d[u].z] > 0; h3 = g_slot[d[u].w] > 0;
                    }
                    int b4 = ii[u] * 4;
                    if (h0) { int p = atomicAdd(&g_l1cnt, 1); if (p < MAX_L1) g_l1e[p] = b4; }
                    if (h1) { int p = atomicAdd(&g_l1cnt, 1); if (p < MAX_L1) g_l1e[p] = b4 + 1; }
                    if (h2) { int p = atomicAdd(&g_l1cnt, 1); if (p < MAX_L1) g_l1e[p] = b4 + 2; }
                    if (h3) { int p = atomicAdd(&g_l1cnt, 1); if (p < MAX_L1) g_l1e[p] = b4 + 3; }
                }
            }
        }
    }
    gbar(2);

    const int m1    = min(g_l1cnt, MAX_L1);
    const int total = m1 + sc1;                        // + self-loops
    const int c0 = lane, c1 = lane + 32;

    // ---- phase D: layer-1 scores + segment max (warp per edge) ------------
    {
        const float Wla0 = Wl1[c0], Wla1 = Wl1[C + c0], bla = bl1[c0];
        const float Wra0 = Wr1[c0], Wra1 = Wr1[C + c0], bra = br1[c0];
        const float Wea  = We1[c0], atta = att1[c0];
        const float Wlb0 = Wl1[c1], Wlb1 = Wl1[C + c1], blb = bl1[c1];
        const float Wrb0 = Wr1[c1], Wrb1 = Wr1[C + c1], brb = br1[c1];
        const float Web  = We1[c1], attb = att1[c1];
        for (int idx = gw; idx < total; idx += NGW) {
            int j, dst; float eav;
            if (idx < m1) { int e = g_l1e[idx]; j = ei[e]; dst = ei[EE + e]; eav = ea[e]; }
            else          { int nd = g_s1[idx - m1]; j = nd; dst = nd; eav = ea_mean; }
            float xj0 = x[2 * j], xj1 = x[2 * j + 1];
            float xd0 = x[2 * dst], xd1 = x[2 * dst + 1];
            float ta = (xj0 * Wla0 + xj1 * Wla1 + bla) + (xd0 * Wra0 + xd1 * Wra1 + bra) + eav * Wea;
            float tb = (xj0 * Wlb0 + xj1 * Wlb1 + blb) + (xd0 * Wrb0 + xd1 * Wrb1 + brb) + eav * Web;
            ta = ta >= 0.f ? ta : NEG * ta;
            tb = tb >= 0.f ? tb : NEG * tb;
            float s = wred(ta * atta + tb * attb);
            if (lane == 0) {
                g_escore[idx] = s;
                atomicMax(&g_nmax[g_slot[dst] - 1], fkey(s));
            }
        }
    }
    gbar(3);

    // ---- phase E: layer-1 softmax weights + segment sums ------------------
    {
        const float Wla0 = Wl1[c0], Wla1 = Wl1[C + c0], bla = bl1[c0];
        const float Wlb0 = Wl1[c1], Wlb1 = Wl1[C + c1], blb = bl1[c1];
        for (int idx = gw; idx < total; idx += NGW) {
            int j, dst;
            if (idx < m1) { int e = g_l1e[idx]; j = ei[e]; dst = ei[EE + e]; }
            else          { int nd = g_s1[idx - m1]; j = nd; dst = nd; }
            int slot = g_slot[dst] - 1;
            float w = expf(g_escore[idx] - finv(g_nmax[slot]));
            float xj0 = x[2 * j], xj1 = x[2 * j + 1];
            float xla = xj0 * Wla0 + xj1 * Wla1 + bla;
            float xlb = xj0 * Wlb0 + xj1 * Wlb1 + blb;
            atomicAdd(&g_nacc[slot * C + c0], w * xla);
            atomicAdd(&g_nacc[slot * C + c1], w * xlb);
            if (lane == 0) atomicAdd(&g_ndenom[slot], w);
        }
    }
    gbar(4);

    // ---- phase F (block 0): finalize h1, layer 2, head, cleanup -----------
    if (bid != 0) {
        __syncthreads();
        if (tid == 0) { __threadfence(); atomicAdd(&g_exit, 1u); }
        return;
    }

    // finalize h1 = relu(acc/denom + b1)
    for (int i = tid; i < sc1 * C; i += NT) {
        float v = g_nacc[i] / g_ndenom[i >> 6] + b1[i & 63];
        g_h1[i] = fmaxf(v, 0.f);
    }
    __syncthreads();

    const int ts = g_slot[tgt] - 1;

    // xr for target
    if (tid < C) {
        const float* h1t = &g_h1[ts * C];
        float a0 = 0.f, a1 = 0.f, a2 = 0.f, a3 = 0.f;
#pragma unroll
        for (int k = 0; k < C; k += 4) {
            a0 += h1t[k]     * Wr2[(k)     * C + tid];
            a1 += h1t[k + 1] * Wr2[(k + 1) * C + tid];
            a2 += h1t[k + 2] * Wr2[(k + 2) * C + tid];
            a3 += h1t[k + 3] * Wr2[(k + 3) * C + tid];
        }
        s_xr[tid] = br2[tid] + ((a0 + a1) + (a2 + a3));
    }
    __syncthreads();

    // layer-2 edges: warp per edge (idx 0 = self-loop)
    const int m2  = min(g_l2cnt, MAX_L2);
    const int deg = min(m2 + 1, MAX_DEG2);
    for (int idx = wid; idx < deg; idx += NWB) {
        int j; float eav;
        if (idx == 0) { j = tgt; eav = ea_mean; }
        else          { int e = g_l2e[idx - 1]; j = ei[e]; eav = ea[e]; }
        const float* hrow = &g_h1[(g_slot[j] - 1) * C];
        float xla = bl2[c0], xlb = bl2[c1];
#pragma unroll 8
        for (int k = 0; k < C; k++) {
            float h = hrow[k];
            xla += h * Wl2[k * C + c0];
            xlb += h * Wl2[k * C + c1];
        }
        float ta = xla + s_xr[c0] + eav * We2[c0];
        float tb = xlb + s_xr[c1] + eav * We2[c1];
        ta = ta >= 0.f ? ta : NEG * ta;
        tb = tb >= 0.f ? tb : NEG * tb;
        float s = wred(ta * att2[c0] + tb * att2[c1]);
        s_xl[idx * C + c0] = xla;
        s_xl[idx * C + c1] = xlb;
        if (lane == 0) s_sc[idx] = s;
    }
    __syncthreads();

    if (tid < C) {
        float smax = -3.4e38f;
        for (int k = 0; k < deg; k++) smax = fmaxf(smax, s_sc[k]);
        float denom = 0.f, acc = 0.f;
        for (int k = 0; k < deg; k++) {
            float w = expf(s_sc[k] - smax);
            denom += w;
            acc   += w * s_xl[k * C + tid];
        }
        s_h2[tid] = fmaxf(acc / denom + b2[tid], 0.f);
    }
    __syncthreads();

    if (tid < HIDN) {
        float o = bf[tid];
#pragma unroll
        for (int k = 0; k < C; k++) o += s_h2[k] * Wf[k * HIDN + tid];
        out[tid] = o;
    }

    // ---- cleanup: restore zero-state for graph replay ---------------------
    __syncthreads();
    for (int i = tid; i < sc1; i += NT) g_slot[g_s1[i]] = 0;
    if (tid == 0) {
        g_l2cnt = 0; g_s1cnt = 0; g_l1cnt = 0; g_easum = 0.f;
        // wait until every other block has arrived past the last barrier
        while (*((volatile unsigned*)&g_exit) < NB - 1) { }
        __threadfence();
#pragma unroll
        for (int k = 0; k < 8; k++) g_barc[k] = 0;
        g_exit = 0;
        __threadfence();
    }
}

extern "C" void kernel_launch(void* const* d_in, const int* in_sizes, int n_in,
                              void* d_out, int out_size) {
    const float* x    = (const float*)d_in[0];
    const int*   ei   = (const int*)d_in[1];
    const float* ea   = (const float*)d_in[2];
    const int*   tgt  = (const int*)d_in[3];
    const float* Wl1  = (const float*)d_in[4];
    const float* bl1  = (const float*)d_in[5];
    const float* Wr1  = (const float*)d_in[6];
    const float* br1  = (const float*)d_in[7];
    const float* We1  = (const float*)d_in[8];
    const float* att1 = (const float*)d_in[9];
    const float* b1   = (const float*)d_in[10];
    const float* Wl2  = (const float*)d_in[11];
    const float* bl2  = (const float*)d_in[12];
    const float* Wr2  = (const float*)d_in[13];
    const float* br2  = (const float*)d_in[14];
    const float* We2  = (const float*)d_in[15];
    const float* att2 = (const float*)d_in[16];
    const float* b2   = (const float*)d_in[17];
    const float* Wf   = (const float*)d_in[18];
    const float* bf   = (const float*)d_in[19];
    float* out = (float*)d_out;

    k_fused<<<NB, NT>>>(x, ei, ea, tgt,
                        Wl1, bl1, Wr1, br1, We1, att1, b1,
                        Wl2, bl2, Wr2, br2, We2, att2, b2,
                        Wf, bf, out);
}